// round 1
// baseline (speedup 1.0000x reference)
#include <cuda_runtime.h>

#define FULL_MASK 0xffffffffu

// Forward-Euler ScaledODENet:
//   ys(0) = 0;  ys(t+1) = ys(t) + (tanh([x_t, ys(t)] @ W1 + b1) @ W2 + b2)/sr
//   out[0, b] = 0 ; out[t, b] = ys_b(t)[0] for t >= 1
//
// One warp (32 threads) per batch element, one CTA per warp -> 32 CTAs spread
// over 32 SMs. Everything lives in registers; the 16-wide state is replicated
// across lanes, the 64-wide hidden layer is distributed 2 units per lane.
__global__ __launch_bounds__(32, 1)
void ode_fe_kernel(const float* __restrict__ x,
                   const float* __restrict__ W1,
                   const float* __restrict__ b1,
                   const float* __restrict__ W2,
                   const float* __restrict__ b2,
                   float* __restrict__ out,
                   int T) {
    constexpr int B = 32;
    const int b = blockIdx.x;    // batch element
    const int l = threadIdx.x;   // lane: owns hidden units l and l+32
    const float inv_sr = 1.0f / 44100.0f;

    // ---- load weights into registers (one-time) ----
    // W1: (17, 64) row-major. Column l and l+32 per lane.
    float w1lo[17], w1hi[17];
    #pragma unroll
    for (int k = 0; k < 17; ++k) {
        w1lo[k] = W1[k * 64 + l];
        w1hi[k] = W1[k * 64 + l + 32];
    }
    const float b1lo = b1[l];
    const float b1hi = b1[l + 32];

    // W2: (64, 16) row-major, pre-scaled by 1/sr. Rows l and l+32 per lane.
    float w2lo[16], w2hi[16], pinit[16], ys[16];
    #pragma unroll
    for (int j = 0; j < 16; ++j) {
        w2lo[j]  = W2[l * 16 + j] * inv_sr;
        w2hi[j]  = W2[(l + 32) * 16 + j] * inv_sr;
        // b2/sr folded into lane 0's partial so the butterfly adds it for free
        pinit[j] = (l == 0) ? b2[j] * inv_sr : 0.0f;
        ys[j]    = 0.0f;
    }

    // out row t=0 is all zeros
    if (l == 0) out[b] = 0.0f;

    const int nsteps = T - 1;

    // x prefetch: block of 32 timesteps per register, one block ahead.
    float xbuf  = (l < nsteps)      ? x[l * B + b]        : 0.0f;
    float xnext = (l + 32 < nsteps) ? x[(l + 32) * B + b] : 0.0f;

    for (int t = 0; t < nsteps; ++t) {
        const float xt = __shfl_sync(FULL_MASK, xbuf, t & 31);

        // ---- hidden pre-activation: a = b1 + x*W1[0,:] + ys @ W1[1:,:] ----
        // 2-way split accumulators to halve the dependent-FMA chain depth.
        float alo0 = fmaf(xt, w1lo[0], b1lo);
        float ahi0 = fmaf(xt, w1hi[0], b1hi);
        float alo1 = 0.0f, ahi1 = 0.0f;
        #pragma unroll
        for (int j = 0; j < 16; j += 2) {
            alo0 = fmaf(ys[j],     w1lo[j + 1], alo0);
            ahi0 = fmaf(ys[j],     w1hi[j + 1], ahi0);
            alo1 = fmaf(ys[j + 1], w1lo[j + 2], alo1);
            ahi1 = fmaf(ys[j + 1], w1hi[j + 2], ahi1);
        }
        const float alo = alo0 + alo1;
        const float ahi = ahi0 + ahi1;

        // ---- tanh(a) = 1 - 2/(exp(2a)+1)  (accurate to ~1e-6 abs) ----
        const float elo = __expf(2.0f * alo);
        const float ehi = __expf(2.0f * ahi);
        const float hlo = 1.0f - __fdividef(2.0f, elo + 1.0f);
        const float hhi = 1.0f - __fdividef(2.0f, ehi + 1.0f);

        // ---- per-lane partial of d/sr = h @ (W2/sr) + b2/sr ----
        float p[16];
        #pragma unroll
        for (int j = 0; j < 16; ++j)
            p[j] = fmaf(hlo, w2lo[j], fmaf(hhi, w2hi[j], pinit[j]));

        // ---- warp butterfly reduce: every lane ends with the full d/sr ----
        #pragma unroll
        for (int off = 16; off > 0; off >>= 1) {
            #pragma unroll
            for (int j = 0; j < 16; ++j)
                p[j] += __shfl_xor_sync(FULL_MASK, p[j], off);
        }

        // ---- state update (replicated identically in all lanes) ----
        #pragma unroll
        for (int j = 0; j < 16; ++j)
            ys[j] += p[j];

        if (l == 0) out[(t + 1) * B + b] = ys[0];

        // refill the x block-ahead buffer (warp-uniform branch, off the
        // critical chain: result is first consumed 32 steps later)
        if ((t & 31) == 31) {
            xbuf = xnext;
            const int tn = t + 33 + l;
            xnext = (tn < nsteps) ? x[tn * B + b] : 0.0f;
        }
    }
}

extern "C" void kernel_launch(void* const* d_in, const int* in_sizes, int n_in,
                              void* d_out, int out_size) {
    const float* x  = (const float*)d_in[0];
    const float* W1 = (const float*)d_in[1];
    const float* b1 = (const float*)d_in[2];
    const float* W2 = (const float*)d_in[3];
    const float* b2 = (const float*)d_in[4];
    float* out = (float*)d_out;

    const int T = in_sizes[0] / 32;  // x is (T, B=32, F=1)
    ode_fe_kernel<<<32, 32>>>(x, W1, b1, W2, b2, out, T);
}